// round 2
// baseline (speedup 1.0000x reference)
#include <cuda_runtime.h>
#include <math.h>

// Problem dims (fixed)
#define B_  64
#define T_  512
#define D_  256
#define H_  256
#define G4  1024          // 4*H
#define NB_SCAN 128       // persistent blocks in scan (<= SM count, all resident)

// ---------------- device scratch (static allocation is allowed) ----------------
__device__ float g_Wc[G4 * D_];              // combined weight W_ih @ W_att  [1024,256]
__device__ float g_bc[G4];                   // combined bias
__device__ float g_vlin0[B_ * D_];           // vlin[:,0]
__device__ float g_a[B_ * T_];               // attention scalars a[b,t]
__device__ float g_alpha[T_ * H_ * B_];      // alpha[t][j][b]  (33.5 MB)
__device__ float g_gates[T_ * G4 * B_];      // input-side gates [t][g][b] (134 MB)
__device__ float g_c0[B_ * H_];              // c_0 from t=0
__device__ float g_hbuf[2 * B_ * H_];        // ping-pong h state
__device__ int   g_flags[NB_SCAN];           // grid-barrier flags

// ---------------- helpers ----------------
__device__ __forceinline__ float sigm(float x) { return 1.0f / (1.0f + expf(-x)); }

__device__ __forceinline__ void st_release(int* p, int v) {
    asm volatile("st.global.release.gpu.b32 [%0], %1;" :: "l"(p), "r"(v) : "memory");
}
__device__ __forceinline__ int ld_acquire(const int* p) {
    int v;
    asm volatile("ld.global.acquire.gpu.b32 %0, [%1];" : "=r"(v) : "l"(p) : "memory");
    return v;
}

// ---------------- kernel: reset barrier flags ----------------
__global__ void k_reset() {
    if (threadIdx.x < NB_SCAN) g_flags[threadIdx.x] = 0;
}

// ---------------- kernel: Wc = W_ih @ W_att ----------------
// grid 1024 blocks (one per gate row), 256 threads (one per k)
__global__ void k_wc(const float* __restrict__ W_ih, const float* __restrict__ W_att) {
    int g = blockIdx.x;
    int k = threadIdx.x;
    __shared__ float wrow[D_];
    wrow[threadIdx.x] = W_ih[g * D_ + threadIdx.x];
    __syncthreads();
    float acc = 0.f;
#pragma unroll 8
    for (int d = 0; d < D_; d++) acc += wrow[d] * W_att[d * D_ + k];
    g_Wc[g * D_ + k] = acc;
}

// ---------------- kernel: bc = W_ih @ b_att + b_ih + b_hh ----------------
__global__ void k_bc(const float* __restrict__ W_ih, const float* __restrict__ b_att,
                     const float* __restrict__ b_ih, const float* __restrict__ b_hh) {
    __shared__ float ba[D_];
    if (threadIdx.x < D_) ba[threadIdx.x] = b_att[threadIdx.x];
    __syncthreads();
    int g = blockIdx.x * blockDim.x + threadIdx.x;
    if (g >= G4) return;
    float acc = b_ih[g] + b_hh[g];
#pragma unroll 8
    for (int d = 0; d < D_; d++) acc += W_ih[g * D_ + d] * ba[d];
    g_bc[g] = acc;
}

// ---------------- kernel: vlin0[b,:] = values[b,0,:] @ W_att^T + b_att ----------------
// grid 64 blocks (one per batch), 256 threads (one per output d)
__global__ void k_vlin0(const float* __restrict__ values, const float* __restrict__ W_att,
                        const float* __restrict__ b_att) {
    int b = blockIdx.x;
    int d = threadIdx.x;
    __shared__ float v[D_];
    v[threadIdx.x] = values[(size_t)b * T_ * D_ + threadIdx.x];
    __syncthreads();
    float acc = b_att[d];
#pragma unroll 8
    for (int k = 0; k < D_; k++) acc += v[k] * W_att[d * D_ + k];
    g_vlin0[b * D_ + d] = acc;
}

// ---------------- kernel: a[b,t] = sigmoid(vlin0[b] . values[b,t]) ----------------
// one warp per (b,t)
__global__ void k_a(const float* __restrict__ values) {
    int w = (blockIdx.x * blockDim.x + threadIdx.x) >> 5;
    int lane = threadIdx.x & 31;
    int b = w >> 9, t = w & (T_ - 1);
    const float* vp = values + ((size_t)b * T_ + t) * D_;
    const float* lp = g_vlin0 + b * D_;
    float acc = 0.f;
#pragma unroll
    for (int k = lane; k < D_; k += 32) acc += vp[k] * lp[k];
#pragma unroll
    for (int off = 16; off; off >>= 1) acc += __shfl_down_sync(0xffffffffu, acc, off);
    if (lane == 0) g_a[w] = sigm(acc);
}

// ---------------- kernel: alpha[t][d][b] = a[b,t] / log(e + cumsum(Deltas)[b,t,d]) ----------------
// grid 64 blocks (one per b), 256 threads (one per d)
__global__ void k_alpha(const float* __restrict__ Deltas) {
    int b = blockIdx.x;
    int d = threadIdx.x;
    const float* dp = Deltas + (size_t)b * T_ * D_ + d;
    float acc = 0.f;
    for (int t = 0; t < T_; t++) {
        acc += dp[(size_t)t * D_];
        float av = g_a[b * T_ + t];
        g_alpha[(size_t)t * (H_ * B_) + d * B_ + b] = av / logf(2.718281828459045f + acc);
    }
}

// ---------------- kernel: big GEMM  gates[t][g][b] = values[b,t,:].Wc[g,:] + bc[g] ----------------
// 64x64 tile per block, 256 threads, 4x4 microtile. grid (T_, 16)
__global__ __launch_bounds__(256) void k_gemm(const float* __restrict__ values) {
    int t  = blockIdx.x;
    int n0 = blockIdx.y * 64;

    __shared__ float As[16 * 65];   // [k][b]
    __shared__ float Bs[16 * 65];   // [k][n]

    int tid = threadIdx.x;
    int tx = tid & 15;              // -> b index
    int ty = tid >> 4;              // -> n index
    int rL = tid >> 2;              // loader row (0..63)
    int kL = (tid & 3) * 4;         // loader k (0,4,8,12)

    float acc[4][4];
#pragma unroll
    for (int i = 0; i < 4; i++)
#pragma unroll
        for (int j = 0; j < 4; j++) acc[i][j] = 0.f;

    for (int k0 = 0; k0 < D_; k0 += 16) {
        float4 av = *(const float4*)&values[((size_t)rL * T_ + t) * D_ + k0 + kL];
        float4 bv = *(const float4*)&g_Wc[(size_t)(n0 + rL) * D_ + k0 + kL];
        __syncthreads();
        As[(kL + 0) * 65 + rL] = av.x;
        As[(kL + 1) * 65 + rL] = av.y;
        As[(kL + 2) * 65 + rL] = av.z;
        As[(kL + 3) * 65 + rL] = av.w;
        Bs[(kL + 0) * 65 + rL] = bv.x;
        Bs[(kL + 1) * 65 + rL] = bv.y;
        Bs[(kL + 2) * 65 + rL] = bv.z;
        Bs[(kL + 3) * 65 + rL] = bv.w;
        __syncthreads();
#pragma unroll
        for (int k = 0; k < 16; k++) {
            float a0 = As[k * 65 + tx];
            float a1 = As[k * 65 + tx + 16];
            float a2 = As[k * 65 + tx + 32];
            float a3 = As[k * 65 + tx + 48];
            float b0 = Bs[k * 65 + ty];
            float b1 = Bs[k * 65 + ty + 16];
            float b2 = Bs[k * 65 + ty + 32];
            float b3 = Bs[k * 65 + ty + 48];
            acc[0][0] += a0 * b0; acc[0][1] += a0 * b1; acc[0][2] += a0 * b2; acc[0][3] += a0 * b3;
            acc[1][0] += a1 * b0; acc[1][1] += a1 * b1; acc[1][2] += a1 * b2; acc[1][3] += a1 * b3;
            acc[2][0] += a2 * b0; acc[2][1] += a2 * b1; acc[2][2] += a2 * b2; acc[2][3] += a2 * b3;
            acc[3][0] += a3 * b0; acc[3][1] += a3 * b1; acc[3][2] += a3 * b2; acc[3][3] += a3 * b3;
        }
    }

    float* outp = g_gates + (size_t)t * (G4 * B_);
#pragma unroll
    for (int j = 0; j < 4; j++) {
        int n = n0 + ty + 16 * j;
        float bias = g_bc[n];
#pragma unroll
        for (int i = 0; i < 4; i++) {
            int b = tx + 16 * i;
            outp[n * B_ + b] = acc[i][j] + bias;
        }
    }
}

// ---------------- kernel: t = 0 cell ----------------
// grid 64 blocks (b), 256 threads (j). h=0, c=0 => gates = input gates.
__global__ void k_t0(float* __restrict__ out) {
    int b = blockIdx.x;
    int j = threadIdx.x;
    float zi = g_gates[(0 * H_ + j) * B_ + b];
    float zf = g_gates[(1 * H_ + j) * B_ + b];  (void)zf; // f*c = 0 since c = 0
    float zg = g_gates[(2 * H_ + j) * B_ + b];
    float zo = g_gates[(3 * H_ + j) * B_ + b];
    float c0 = sigm(zi) * tanhf(zg);
    float h1 = sigm(zo) * tanhf(c0);
    g_c0[b * H_ + j] = c0;
    g_hbuf[0 * (B_ * H_) + b * H_ + j] = h1;              // buffer 0 = h after t=0
    out[(size_t)b * T_ * H_ + 0 * H_ + j] = h1;
}

// ---------------- persistent scan kernel ----------------
// NB_SCAN=128 blocks x 256 threads. Block bid owns hidden units j0=2*bid, j0+1.
// SMEM: h_s[64][260] (float4-friendly pad), w_s[8][260], gsm[8][64]
#define HPAD 260
__global__ __launch_bounds__(256) void k_scan(const float* __restrict__ Whh,
                                              float* __restrict__ out) {
    extern __shared__ float sm[];
    float* h_s = sm;                       // 64 * 260
    float* w_s = sm + 64 * HPAD;           // 8 * 260
    float* gsm = w_s + 8 * HPAD;           // 8 * 64

    int tid = threadIdx.x;
    int bid = blockIdx.x;
    int j0 = bid * 2;

    // preload W_hh slice: local row r = q*2+u  -> global gate row q*256 + j0 + u
    for (int i = tid; i < 8 * 256; i += 256) {
        int r = i >> 8, k = i & 255;
        int grow = ((r >> 1) * H_) + j0 + (r & 1);
        w_s[r * HPAD + k] = Whh[grow * H_ + k];
    }

    int b = tid >> 2;          // dot-phase batch
    int q = tid & 3;           // gate quadrant (i,f,g,o)

    int bu = 0, uu = 0;
    float c_reg = 0.f, c0_reg = 0.f;
    if (tid < 128) {
        bu = tid >> 1;
        uu = tid & 1;
        c0_reg = g_c0[bu * H_ + j0 + uu];
    }
    __syncthreads();

    for (int t = 1; t < T_; t++) {
        int rbuf = (t - 1) & 1, wbuf = t & 1;

        // cooperative load of h into SMEM (float4)
        const float4* hg = (const float4*)(g_hbuf + rbuf * (B_ * H_));
        for (int i = tid; i < (B_ * H_) / 4; i += 256) {
            float4 v = hg[i];
            int bb = i >> 6, kk = (i & 63) << 2;
            *(float4*)&h_s[bb * HPAD + kk] = v;
        }

        // prefetch input gates + alpha for update threads
        float gin0 = 0.f, gin1 = 0.f, gin2 = 0.f, gin3 = 0.f, al = 0.f;
        if (tid < 128) {
            const float* gt = g_gates + (size_t)t * (G4 * B_);
            int jj = j0 + uu;
            gin0 = gt[(0 * H_ + jj) * B_ + bu];
            gin1 = gt[(1 * H_ + jj) * B_ + bu];
            gin2 = gt[(2 * H_ + jj) * B_ + bu];
            gin3 = gt[(3 * H_ + jj) * B_ + bu];
            al   = g_alpha[(size_t)t * (H_ * B_) + jj * B_ + bu];
        }
        __syncthreads();

        // dot: gates for (b, unit j0) and (b, unit j0+1), quadrant q
        {
            const float4* hp = (const float4*)&h_s[b * HPAD];
            const float4* w0 = (const float4*)&w_s[(q * 2 + 0) * HPAD];
            const float4* w1 = (const float4*)&w_s[(q * 2 + 1) * HPAD];
            float s0 = 0, s1 = 0, s2 = 0, s3 = 0;
            float r0 = 0, r1 = 0, r2 = 0, r3 = 0;
#pragma unroll 16
            for (int k = 0; k < 64; k++) {
                float4 h = hp[k];
                float4 x = w0[k];
                float4 y = w1[k];
                s0 += h.x * x.x; s1 += h.y * x.y; s2 += h.z * x.z; s3 += h.w * x.w;
                r0 += h.x * y.x; r1 += h.y * y.y; r2 += h.z * y.z; r3 += h.w * y.w;
            }
            gsm[(q * 2 + 0) * 64 + b] = (s0 + s1) + (s2 + s3);
            gsm[(q * 2 + 1) * 64 + b] = (r0 + r1) + (r2 + r3);
        }
        __syncthreads();

        // cell update (threads 0..127: one per (b, unit))
        if (tid < 128) {
            float zi = gin0 + gsm[(0 + uu) * 64 + bu];
            float zf = gin1 + gsm[(2 + uu) * 64 + bu];
            float zg = gin2 + gsm[(4 + uu) * 64 + bu];
            float zo = gin3 + gsm[(6 + uu) * 64 + bu];
            float c = al * c0_reg + (1.f - al) * c_reg;
            c = sigm(zf) * c + sigm(zi) * tanhf(zg);
            c_reg = c;
            float h = sigm(zo) * tanhf(c);
            int jj = j0 + uu;
            g_hbuf[wbuf * (B_ * H_) + bu * H_ + jj] = h;
            out[(size_t)bu * T_ * H_ + (size_t)t * H_ + jj] = h;
        }

        // grid barrier (release/acquire flag array)
        __syncthreads();
        if (tid == 0) st_release(&g_flags[bid], t);
        if (tid < NB_SCAN) {
            while (ld_acquire(&g_flags[tid]) < t) { }
        }
        __syncthreads();
    }
}

// ---------------- launch ----------------
extern "C" void kernel_launch(void* const* d_in, const int* in_sizes, int n_in,
                              void* d_out, int out_size) {
    (void)in_sizes; (void)n_in; (void)out_size;
    const float* values = (const float*)d_in[0];
    const float* Deltas = (const float*)d_in[1];
    const float* W_att  = (const float*)d_in[2];
    const float* b_att  = (const float*)d_in[3];
    const float* W_ih   = (const float*)d_in[4];
    const float* W_hh   = (const float*)d_in[5];
    const float* b_ih   = (const float*)d_in[6];
    const float* b_hh   = (const float*)d_in[7];
    float* out = (float*)d_out;

    static bool attr_set = false;
    if (!attr_set) {
        cudaFuncSetAttribute(k_scan, cudaFuncAttributeMaxDynamicSharedMemorySize,
                             (64 * HPAD + 8 * HPAD + 8 * 64) * 4);
        attr_set = true;
    }

    k_reset<<<1, NB_SCAN>>>();
    k_wc<<<G4, D_>>>(W_ih, W_att);
    k_bc<<<G4 / 256, 256>>>(W_ih, b_att, b_ih, b_hh);
    k_vlin0<<<B_, D_>>>(values, W_att, b_att);
    k_a<<<(B_ * T_ * 32) / 256, 256>>>(values);
    k_alpha<<<B_, D_>>>(Deltas);
    k_gemm<<<dim3(T_, G4 / 64), 256>>>(values);
    k_t0<<<B_, H_>>>(out);

    size_t smem = (size_t)(64 * HPAD + 8 * HPAD + 8 * 64) * 4;
    k_scan<<<NB_SCAN, 256, smem>>>(W_hh, out);
}

// round 3
// speedup vs baseline: 1.4956x; 1.4956x over previous
#include <cuda_runtime.h>
#include <math.h>

// Problem dims (fixed)
#define B_  64
#define T_  512
#define D_  256
#define H_  256
#define G4  1024          // 4*H
#define NB_SCAN 128       // persistent blocks in scan (all co-resident, 1/SM)

// ---------------- device scratch ----------------
__device__ float g_Wc[G4 * D_];              // combined weight W_ih @ W_att  [1024,256]
__device__ float g_bc[G4];                   // combined bias
__device__ float g_vlin0[B_ * D_];           // vlin[:,0]
__device__ float g_a[B_ * T_];               // attention scalars a[b,t]
__device__ float g_alpha[(size_t)T_ * H_ * B_];   // alpha[t][j][b]
__device__ float g_gates[(size_t)T_ * G4 * B_];   // input-side gates [t][grow][b]
__device__ float g_hbuf[2 * H_ * B_];        // ping-pong h state, layout [j][b]
__device__ int   g_flags[NB_SCAN];           // grid-barrier flags

// ---------------- helpers ----------------
__device__ __forceinline__ float sigm(float x) { return 1.0f / (1.0f + expf(-x)); }

__device__ __forceinline__ void st_release(int* p, int v) {
    asm volatile("st.global.release.gpu.b32 [%0], %1;" :: "l"(p), "r"(v) : "memory");
}
__device__ __forceinline__ int ld_acquire(const int* p) {
    int v;
    asm volatile("ld.global.acquire.gpu.b32 %0, [%1];" : "=r"(v) : "l"(p) : "memory");
    return v;
}

// ---------------- kernel: reset barrier flags ----------------
__global__ void k_reset() {
    if (threadIdx.x < NB_SCAN) g_flags[threadIdx.x] = 0;
}

// ---------------- kernel: Wc = W_ih @ W_att ----------------
__global__ void k_wc(const float* __restrict__ W_ih, const float* __restrict__ W_att) {
    int g = blockIdx.x;
    int k = threadIdx.x;
    __shared__ float wrow[D_];
    wrow[threadIdx.x] = W_ih[g * D_ + threadIdx.x];
    __syncthreads();
    float acc = 0.f;
#pragma unroll 8
    for (int d = 0; d < D_; d++) acc += wrow[d] * W_att[d * D_ + k];
    g_Wc[g * D_ + k] = acc;
}

// ---------------- kernel: bc = W_ih @ b_att + b_ih + b_hh ----------------
__global__ void k_bc(const float* __restrict__ W_ih, const float* __restrict__ b_att,
                     const float* __restrict__ b_ih, const float* __restrict__ b_hh) {
    __shared__ float ba[D_];
    if (threadIdx.x < D_) ba[threadIdx.x] = b_att[threadIdx.x];
    __syncthreads();
    int g = blockIdx.x * blockDim.x + threadIdx.x;
    if (g >= G4) return;
    float acc = b_ih[g] + b_hh[g];
#pragma unroll 8
    for (int d = 0; d < D_; d++) acc += W_ih[g * D_ + d] * ba[d];
    g_bc[g] = acc;
}

// ---------------- kernel: vlin0[b,:] = values[b,0,:] @ W_att^T + b_att ----------------
__global__ void k_vlin0(const float* __restrict__ values, const float* __restrict__ W_att,
                        const float* __restrict__ b_att) {
    int b = blockIdx.x;
    int d = threadIdx.x;
    __shared__ float v[D_];
    v[threadIdx.x] = values[(size_t)b * T_ * D_ + threadIdx.x];
    __syncthreads();
    float acc = b_att[d];
#pragma unroll 8
    for (int k = 0; k < D_; k++) acc += v[k] * W_att[d * D_ + k];
    g_vlin0[b * D_ + d] = acc;
}

// ---------------- kernel: a[b,t] = sigmoid(vlin0[b] . values[b,t]) ----------------
__global__ void k_a(const float* __restrict__ values) {
    int w = (blockIdx.x * blockDim.x + threadIdx.x) >> 5;
    int lane = threadIdx.x & 31;
    int b = w >> 9, t = w & (T_ - 1);
    const float* vp = values + ((size_t)b * T_ + t) * D_;
    const float* lp = g_vlin0 + b * D_;
    float acc = 0.f;
#pragma unroll
    for (int k = lane; k < D_; k += 32) acc += vp[k] * lp[k];
#pragma unroll
    for (int off = 16; off; off >>= 1) acc += __shfl_down_sync(0xffffffffu, acc, off);
    if (lane == 0) g_a[w] = sigm(acc);
}

// ---------------- kernel: alpha[t][d][b] = a[b,t] / log(e + cumsum(Deltas)[b,t,d]) ----------------
__global__ void k_alpha(const float* __restrict__ Deltas) {
    int b = blockIdx.x;
    int d = threadIdx.x;
    const float* dp = Deltas + (size_t)b * T_ * D_ + d;
    float acc = 0.f;
    for (int t = 0; t < T_; t++) {
        acc += dp[(size_t)t * D_];
        float av = g_a[b * T_ + t];
        g_alpha[(size_t)t * (H_ * B_) + d * B_ + b] = av / logf(2.718281828459045f + acc);
    }
}

// ---------------- kernel: big GEMM  gates[t][g][b] = values[b,t,:].Wc[g,:] + bc[g] ----------------
// 64(batch)x64(n) tile per block, 256 threads, 4x4 microtile, float4 SMEM reads,
// 32-wide k chunks with register-prefetch pipeline. grid (T_, 16)
#define KP 68   // smem row pitch (floats); 68*4=272B, multiple of 16 -> float4-aligned
__global__ __launch_bounds__(256) void k_gemm(const float* __restrict__ values) {
    int t  = blockIdx.x;
    int n0 = blockIdx.y * 64;

    __shared__ float As[32 * KP];   // [k][b]
    __shared__ float Bs[32 * KP];   // [k][n]

    int tid = threadIdx.x;
    int tx = tid & 15;              // batch quad
    int ty = tid >> 4;              // n quad
    int rL = tid >> 2;              // loader row (0..63)
    int fq = tid & 3;               // loader float4 col (plus +4)

    const float* aG = values + ((size_t)rL * T_ + t) * D_;
    const float* bG = g_Wc + (size_t)(n0 + rL) * D_;

    float acc[4][4];
#pragma unroll
    for (int i = 0; i < 4; i++)
#pragma unroll
        for (int j = 0; j < 4; j++) acc[i][j] = 0.f;

    float4 ca0 = *(const float4*)(aG + fq * 4);
    float4 ca1 = *(const float4*)(aG + (fq + 4) * 4);
    float4 cb0 = *(const float4*)(bG + fq * 4);
    float4 cb1 = *(const float4*)(bG + (fq + 4) * 4);

    for (int c = 0; c < 8; c++) {
        __syncthreads();
        // scatter-store (transpose to [k][row])
        As[(fq * 4 + 0) * KP + rL] = ca0.x;
        As[(fq * 4 + 1) * KP + rL] = ca0.y;
        As[(fq * 4 + 2) * KP + rL] = ca0.z;
        As[(fq * 4 + 3) * KP + rL] = ca0.w;
        As[((fq + 4) * 4 + 0) * KP + rL] = ca1.x;
        As[((fq + 4) * 4 + 1) * KP + rL] = ca1.y;
        As[((fq + 4) * 4 + 2) * KP + rL] = ca1.z;
        As[((fq + 4) * 4 + 3) * KP + rL] = ca1.w;
        Bs[(fq * 4 + 0) * KP + rL] = cb0.x;
        Bs[(fq * 4 + 1) * KP + rL] = cb0.y;
        Bs[(fq * 4 + 2) * KP + rL] = cb0.z;
        Bs[(fq * 4 + 3) * KP + rL] = cb0.w;
        Bs[((fq + 4) * 4 + 0) * KP + rL] = cb1.x;
        Bs[((fq + 4) * 4 + 1) * KP + rL] = cb1.y;
        Bs[((fq + 4) * 4 + 2) * KP + rL] = cb1.z;
        Bs[((fq + 4) * 4 + 3) * KP + rL] = cb1.w;
        __syncthreads();

        float4 na0, na1, nb0, nb1;
        if (c < 7) {
            int k0 = (c + 1) * 32;
            na0 = *(const float4*)(aG + k0 + fq * 4);
            na1 = *(const float4*)(aG + k0 + (fq + 4) * 4);
            nb0 = *(const float4*)(bG + k0 + fq * 4);
            nb1 = *(const float4*)(bG + k0 + (fq + 4) * 4);
        } else {
            na0 = na1 = nb0 = nb1 = make_float4(0.f, 0.f, 0.f, 0.f);
        }

#pragma unroll 8
        for (int k = 0; k < 32; k++) {
            float4 af = *(const float4*)&As[k * KP + 4 * tx];
            float4 bf = *(const float4*)&Bs[k * KP + 4 * ty];
            acc[0][0] += af.x * bf.x; acc[0][1] += af.x * bf.y; acc[0][2] += af.x * bf.z; acc[0][3] += af.x * bf.w;
            acc[1][0] += af.y * bf.x; acc[1][1] += af.y * bf.y; acc[1][2] += af.y * bf.z; acc[1][3] += af.y * bf.w;
            acc[2][0] += af.z * bf.x; acc[2][1] += af.z * bf.y; acc[2][2] += af.z * bf.z; acc[2][3] += af.z * bf.w;
            acc[3][0] += af.w * bf.x; acc[3][1] += af.w * bf.y; acc[3][2] += af.w * bf.z; acc[3][3] += af.w * bf.w;
        }
        ca0 = na0; ca1 = na1; cb0 = nb0; cb1 = nb1;
    }

    float* outp = g_gates + (size_t)t * (G4 * B_);
#pragma unroll
    for (int j = 0; j < 4; j++) {
        int n = n0 + 4 * ty + j;
        float bias = g_bc[n];
        float4 v = make_float4(acc[0][j] + bias, acc[1][j] + bias,
                               acc[2][j] + bias, acc[3][j] + bias);
        *(float4*)&outp[n * B_ + 4 * tx] = v;
    }
}

// ---------------- persistent scan kernel ----------------
// NB_SCAN=128 blocks x 256 threads. Block bid owns hidden units j0=2*bid, j0+1
// (local gate rows r = q*2+u -> global row q*H_ + j0 + u).
// SMEM (dynamic 76KB): h_s[256][64] (k-major, = linear copy of g_hbuf[j][b]),
//                      w_s[8][256], psum[2][8][64]
__global__ __launch_bounds__(256) void k_scan(const float* __restrict__ Whh,
                                              float* __restrict__ out) {
    extern __shared__ float sm[];
    float* h_s  = sm;                       // 16384 floats (64KB)
    float* w_s  = sm + H_ * B_;             // 2048 floats
    float* psum = w_s + 8 * H_;             // 1024 floats  [s][r][b]

    int tid = threadIdx.x;
    int bid = blockIdx.x;
    int j0 = bid * 2;

    // preload W_hh slice into SMEM: local row r -> global row (r>>1)*H_ + j0 + (r&1)
    for (int i = tid; i < 8 * H_; i += 256) {
        int r = i >> 8, k = i & (H_ - 1);
        int grow = ((r >> 1) * H_) + j0 + (r & 1);
        w_s[r * H_ + k] = Whh[grow * H_ + k];
    }

    // dot-phase identity
    int lane = tid & 31;
    int wrp  = tid >> 5;
    int rq = wrp & 1;          // row quad (rows 4rq..4rq+3)
    int bh = (wrp >> 1) & 1;   // batch half
    int s  = wrp >> 2;         // k half
    int bd = bh * 32 + lane;   // batch for dot
    const float* w0p = w_s + (4 * rq + 0) * H_ + s * 128;
    const float* w1p = w0p + H_;
    const float* w2p = w0p + 2 * H_;
    const float* w3p = w0p + 3 * H_;
    const float* hkp = h_s + (size_t)(s * 128) * B_ + bd;

    // update-phase identity
    int u  = tid >> 6;         // valid for tid<128
    int bu = tid & 63;
    int jj = j0 + u;

    float c_reg = 0.f, c0_reg = 0.f;

    // ---- prologue: t = 0 (h=0, c=0; carry c stays zero — faithful quirk) ----
    if (tid < 128) {
        const float* g0 = g_gates;
        float zi = g0[(0 * H_ + jj) * B_ + bu];
        float zg = g0[(2 * H_ + jj) * B_ + bu];
        float zo = g0[(3 * H_ + jj) * B_ + bu];
        c0_reg = sigm(zi) * tanhf(zg);
        float h1 = sigm(zo) * tanhf(c0_reg);
        g_hbuf[jj * B_ + bu] = h1;                 // buffer 0, layout [j][b]
        out[(size_t)bu * T_ * H_ + jj] = h1;
    }
    __syncthreads();
    if (tid == 0) st_release(&g_flags[bid], 1);

    for (int t = 1; t < T_; t++) {
        // prefetch input gates + alpha (independent of barrier) to hide latency
        float gin0 = 0.f, gin1 = 0.f, gin2 = 0.f, gin3 = 0.f, al = 0.f;
        if (tid < 128) {
            const float* gt = g_gates + (size_t)t * (G4 * B_);
            gin0 = gt[(0 * H_ + jj) * B_ + bu];
            gin1 = gt[(1 * H_ + jj) * B_ + bu];
            gin2 = gt[(2 * H_ + jj) * B_ + bu];
            gin3 = gt[(3 * H_ + jj) * B_ + bu];
            al   = g_alpha[(size_t)t * (H_ * B_) + jj * B_ + bu];
        }

        // grid barrier: wait for all blocks to have published h(t-1)
        if (tid < NB_SCAN) {
            while (ld_acquire(&g_flags[tid]) < t) { }
        }
        __syncthreads();

        // stage h(t-1): straight 64KB float4 copy ([j][b] global == [k][b] smem)
        {
            const float4* hg = (const float4*)(g_hbuf + ((t - 1) & 1) * (H_ * B_));
            float4* hs4 = (float4*)h_s;
            for (int i = tid; i < (H_ * B_) / 4; i += 256) hs4[i] = hg[i];
        }
        __syncthreads();

        // dot: 4 rows x 1 batch x 128 k per thread
        {
            float a0 = 0.f, a1 = 0.f, a2 = 0.f, a3 = 0.f;
#pragma unroll 8
            for (int k4 = 0; k4 < 32; k4++) {
                float4 wv0 = *(const float4*)(w0p + 4 * k4);
                float4 wv1 = *(const float4*)(w1p + 4 * k4);
                float4 wv2 = *(const float4*)(w2p + 4 * k4);
                float4 wv3 = *(const float4*)(w3p + 4 * k4);
                float h0 = hkp[(4 * k4 + 0) * B_];
                float h1 = hkp[(4 * k4 + 1) * B_];
                float h2 = hkp[(4 * k4 + 2) * B_];
                float h3 = hkp[(4 * k4 + 3) * B_];
                a0 += h0 * wv0.x + h1 * wv0.y + h2 * wv0.z + h3 * wv0.w;
                a1 += h0 * wv1.x + h1 * wv1.y + h2 * wv1.z + h3 * wv1.w;
                a2 += h0 * wv2.x + h1 * wv2.y + h2 * wv2.z + h3 * wv2.w;
                a3 += h0 * wv3.x + h1 * wv3.y + h2 * wv3.z + h3 * wv3.w;
            }
            float* ps = psum + s * (8 * B_);
            ps[(4 * rq + 0) * B_ + bd] = a0;
            ps[(4 * rq + 1) * B_ + bd] = a1;
            ps[(4 * rq + 2) * B_ + bd] = a2;
            ps[(4 * rq + 3) * B_ + bd] = a3;
        }
        __syncthreads();

        // cell update: threads 0..127, one per (b, unit)
        if (tid < 128) {
            int r0 = (0 * 2 + u) * B_ + bu;
            int r1 = (1 * 2 + u) * B_ + bu;
            int r2 = (2 * 2 + u) * B_ + bu;
            int r3 = (3 * 2 + u) * B_ + bu;
            float zi = gin0 + psum[r0] + psum[8 * B_ + r0];
            float zf = gin1 + psum[r1] + psum[8 * B_ + r1];
            float zg = gin2 + psum[r2] + psum[8 * B_ + r2];
            float zo = gin3 + psum[r3] + psum[8 * B_ + r3];
            float c = al * c0_reg + (1.f - al) * c_reg;
            c = sigm(zf) * c + sigm(zi) * tanhf(zg);
            c_reg = c;
            float h = sigm(zo) * tanhf(c);
            g_hbuf[(t & 1) * (H_ * B_) + jj * B_ + bu] = h;
            out[(size_t)bu * T_ * H_ + (size_t)t * H_ + jj] = h;
        }

        __syncthreads();
        if (tid == 0) st_release(&g_flags[bid], t + 1);
    }
}

// ---------------- launch ----------------
extern "C" void kernel_launch(void* const* d_in, const int* in_sizes, int n_in,
                              void* d_out, int out_size) {
    (void)in_sizes; (void)n_in; (void)out_size;
    const float* values = (const float*)d_in[0];
    const float* Deltas = (const float*)d_in[1];
    const float* W_att  = (const float*)d_in[2];
    const float* b_att  = (const float*)d_in[3];
    const float* W_ih   = (const float*)d_in[4];
    const float* W_hh   = (const float*)d_in[5];
    const float* b_ih   = (const float*)d_in[6];
    const float* b_hh   = (const float*)d_in[7];
    float* out = (float*)d_out;

    size_t smem = (size_t)(H_ * B_ + 8 * H_ + 2 * 8 * B_) * 4;   // 77824 B
    cudaFuncSetAttribute(k_scan, cudaFuncAttributeMaxDynamicSharedMemorySize, (int)smem);

    // order chosen so the profiled launch (index ~4) is k_gemm
    k_wc<<<G4, D_>>>(W_ih, W_att);
    k_bc<<<G4 / 256, 256>>>(W_ih, b_att, b_ih, b_hh);
    k_vlin0<<<B_, D_>>>(values, W_att, b_att);
    k_gemm<<<dim3(T_, G4 / 64), 256>>>(values);
    k_a<<<(B_ * T_ * 32) / 256, 256>>>(values);
    k_alpha<<<B_, D_>>>(Deltas);
    k_reset<<<1, NB_SCAN>>>();
    k_scan<<<NB_SCAN, 256, smem>>>(W_hh, out);
}